// round 14
// baseline (speedup 1.0000x reference)
#include <cuda_runtime.h>
#include <stdint.h>

#define NCLS   10
#define DD     128
#define TROWS  64                  // rows per tile
#define STAGES 4
#define THR    256
#define NBLK   148                 // 1 block/SM, one wave

#define X_TILE_F (TROWS * DD)      // floats per x tile (8192)
#define X_TILE_B (X_TILE_F * 4)    // 32768 bytes
#define L_TILE_W TROWS             // label words per tile

// dynamic smem: xs | labs | mbar | hist | seg | qb | sidx
#define SMEM_DYN (STAGES * X_TILE_B + STAGES * L_TILE_W * 4 + STAGES * 8 + \
                  32 * 4 + 12 * 4 + NCLS * 4 + 64 + 128)

// Zero-initialized at module load; finalizing block re-zeros after each use.
__device__ float g_sums[NCLS * DD];
__device__ float g_rssq[NCLS];
__device__ float g_cnt[NCLS];
__device__ unsigned int g_ticket;

__device__ __forceinline__ uint32_t s2u(const void* p) {
    uint32_t a;
    asm("{ .reg .u64 t; cvta.to.shared.u64 t, %1; cvt.u32.u64 %0, t; }"
        : "=r"(a) : "l"(p));
    return a;
}

#define MB_WAIT(mb, ph) do {                                                  \
    unsigned _done;                                                           \
    asm volatile("{\n\t.reg .pred p;\n\t"                                     \
        "mbarrier.try_wait.parity.acquire.cta.shared::cta.b64 p, [%1], %2;\n\t" \
        "selp.b32 %0,1,0,p;\n\t}"                                             \
        : "=r"(_done) : "r"(mb), "r"(ph) : "memory");                         \
    while (!_done) {                                                          \
        asm volatile("{\n\t.reg .pred p;\n\t"                                 \
            "mbarrier.try_wait.parity.acquire.cta.shared::cta.b64 p, [%1], %2, 0x989680;\n\t" \
            "selp.b32 %0,1,0,p;\n\t}"                                         \
            : "=r"(_done) : "r"(mb), "r"(ph) : "memory");                     \
    }                                                                         \
} while (0)

extern __shared__ float dynsm[];

__global__ __launch_bounds__(THR) void acc_k(const float* __restrict__ x,
                                             const int* __restrict__ t,
                                             int n, float* __restrict__ out) {
    // ── dynamic smem carve-up ──
    float* xs   = dynsm;                                    // STAGES*8192 floats
    int*   labs = (int*)(xs + STAGES * X_TILE_F);           // STAGES*64 ints
    unsigned long long* mbar = (unsigned long long*)(labs + STAGES * L_TILE_W);
    int*   hist = (int*)(mbar + STAGES);                    // [2][16]
    int*   seg  = hist + 32;                                // [12]
    float* qb   = (float*)(seg + 12);                       // [10]
    unsigned char* sidx = (unsigned char*)(qb + NCLS);      // [64]
    __shared__ bool s_last;

    const int tid  = threadIdx.x;
    const int lane = tid & 31;
    const int w    = tid >> 5;
    const int f    = tid & 127;          // feature owned by this thread
    const int g    = tid >> 7;           // row-parity group (0/1)

    // block's contiguous tile range
    const int NT   = (n + TROWS - 1) / TROWS;
    const int base = NT / NBLK, rem = NT % NBLK;
    const int nt_blk = base + ((int)blockIdx.x < rem ? 1 : 0);
    const int g0 = (int)blockIdx.x * base + ((int)blockIdx.x < rem ? (int)blockIdx.x : rem);

    if (tid == 0) {
        for (int s = 0; s < STAGES; s++)
            asm volatile("mbarrier.init.shared.b64 [%0], 1;"
                         :: "r"(s2u(mbar + s)) : "memory");
    }
    if (tid < NCLS) qb[tid] = 0.0f;
    __syncthreads();

    // producer: bulk-copy tile (local index k) into its ring slot
    auto issue = [&](int k) {
        const int gt   = g0 + k;
        const int rows = min(TROWS, n - gt * TROWS);
        const int xb   = rows * DD * 4;
        const int lb   = (rows * 4) & ~15;          // 16B-aligned label bytes
        const uint32_t mb = s2u(mbar + (k % STAGES));
        asm volatile("mbarrier.arrive.expect_tx.shared.b64 _, [%0], %1;"
                     :: "r"(mb), "r"(xb + lb) : "memory");
        const uint32_t xd = s2u(xs + (k % STAGES) * X_TILE_F);
        asm volatile("cp.async.bulk.shared::cluster.global.mbarrier::complete_tx::bytes "
                     "[%0], [%1], %2, [%3];"
                     :: "r"(xd), "l"(x + (size_t)gt * TROWS * DD), "r"(xb), "r"(mb)
                     : "memory");
        if (lb) {
            const uint32_t ld = s2u(labs + (k % STAGES) * L_TILE_W);
            asm volatile("cp.async.bulk.shared::cluster.global.mbarrier::complete_tx::bytes "
                         "[%0], [%1], %2, [%3];"
                         :: "r"(ld), "l"(t + (size_t)gt * TROWS), "r"(lb), "r"(mb)
                         : "memory");
        }
    };

    if (tid == 0) {
        const int pre = (nt_blk < STAGES - 1) ? nt_blk : STAGES - 1;
        for (int k = 0; k < pre; k++) issue(k);
    }

    // per-thread persistent accumulators (compile-time indexed → registers)
    float acc[NCLS], q[NCLS];
#pragma unroll
    for (int c = 0; c < NCLS; c++) { acc[c] = 0.0f; q[c] = 0.0f; }
    int mycnt = 0;                      // thread tid<10 tracks class tid's count

    for (int k = 0; k < nt_blk; k++) {
        const int slot = k % STAGES;
        const int ph   = (k / STAGES) & 1;
        MB_WAIT(s2u(mbar + slot), ph);

        const int gt   = g0 + k;
        const int rows = min(TROWS, n - gt * TROWS);
        const int lb4  = ((rows * 4) & ~15) >> 2;

        // ── deterministic ballot counting-sort of the tile's labels ──
        int lab = -1, rank = 0;
        if (tid < TROWS) {
            if (tid < lb4)      lab = labs[slot * L_TILE_W + tid];
            else if (tid < rows) lab = __ldg(t + (size_t)gt * TROWS + tid);
        }
        if (tid < 64) {
            const unsigned lt = (1u << lane) - 1u;
#pragma unroll
            for (int c = 0; c < NCLS; c++) {
                unsigned m = __ballot_sync(0xffffffffu, lab == c);
                if (lab == c)  rank = __popc(m & lt);
                if (lane == c) hist[w * 16 + c] = __popc(m);
            }
        }
        __syncthreads();
        if (tid == 0) {
            int s = 0;
#pragma unroll
            for (int c = 0; c < NCLS; c++) { seg[c] = s; s += hist[c] + hist[16 + c]; }
            seg[NCLS] = s;
        }
        __syncthreads();
        if (tid < NCLS) mycnt += hist[tid] + hist[16 + tid];
        if (tid < 64 && lab >= 0) {
            const int pos = seg[lab] + (w ? hist[lab] : 0) + rank;
            sidx[pos] = (unsigned char)tid;
        }
        __syncthreads();

        // ── reduce: thread owns feature f; walk sorted rows per class ──
        const float* xt = xs + slot * X_TILE_F;
#pragma unroll
        for (int c = 0; c < NCLS; c++) {
            const int je = seg[c + 1];
            for (int j = seg[c] + g; j < je; j += 2) {
                const float v = xt[(int)sidx[j] * DD + f];
                acc[c] += v;
                q[c] = fmaf(v, v, q[c]);
            }
        }
        __syncthreads();   // tile fully consumed: slot reusable

        if (tid == 0 && k + STAGES - 1 < nt_blk) issue(k + STAGES - 1);
    }

    // ── block combine: fold g=1 partials into g=0, then flush ──
    float* red = xs;                      // ring no longer needed
    if (g == 1) {
#pragma unroll
        for (int c = 0; c < NCLS; c++) red[c * DD + f] = acc[c];
    }
    __syncthreads();
    if (g == 0) {
#pragma unroll
        for (int c = 0; c < NCLS; c++)
            atomicAdd(&g_sums[c * DD + f], acc[c] + red[c * DD + f]);
    }
#pragma unroll
    for (int c = 0; c < NCLS; c++) {
        float v = q[c];
        v += __shfl_xor_sync(0xffffffffu, v, 16);
        v += __shfl_xor_sync(0xffffffffu, v, 8);
        v += __shfl_xor_sync(0xffffffffu, v, 4);
        v += __shfl_xor_sync(0xffffffffu, v, 2);
        v += __shfl_xor_sync(0xffffffffu, v, 1);
        if (lane == 0) atomicAdd(&qb[c], v);
    }
    __syncthreads();
    if (tid < NCLS) {
        atomicAdd(&g_rssq[tid], qb[tid]);
        atomicAdd(&g_cnt[tid], (float)mycnt);
    }

    // ── last-block finalization (fused; proven pattern) ──
    __threadfence();
    if (tid == 0)
        s_last = (atomicAdd(&g_ticket, 1u) == (unsigned)(gridDim.x - 1));
    __syncthreads();
    if (!s_last) return;

    float* cross = xs + 4096;             // fresh scratch region
    if (tid < NCLS) cross[tid] = 0.0f;
    __syncthreads();
    if (tid < DD) {
#pragma unroll
        for (int c = 0; c < NCLS; c++) {
            const float s = g_sums[c * DD + tid];
            atomicAdd(&cross[c], s * s);
            g_sums[c * DD + tid] = 0.0f;  // re-zero for next replay
        }
    }
    __syncthreads();
    if (tid == 0) {
        float a = 0.0f;
#pragma unroll
        for (int c = 0; c < NCLS; c++) {
            const float ncf = g_cnt[c];
            a += (g_rssq[c] - cross[c] / ncf) / (ncf - 1.0f);
            g_rssq[c] = 0.0f;
            g_cnt[c]  = 0.0f;
        }
        out[0] = a / (float)NCLS;
        g_ticket = 0u;
    }
}

extern "C" void kernel_launch(void* const* d_in, const int* in_sizes, int n_in,
                              void* d_out, int out_size) {
    const float* x = (const float*)d_in[0];   // x: [N, 128] fp32
    const int*   t = (const int*)d_in[1];     // t: [N] int32
    const int n = in_sizes[1];                // N = row count

    cudaFuncSetAttribute(acc_k, cudaFuncAttributeMaxDynamicSharedMemorySize, SMEM_DYN);
    acc_k<<<NBLK, THR, SMEM_DYN>>>(x, t, n, (float*)d_out);
}

// round 17
// speedup vs baseline: 2.6395x; 2.6395x over previous
#include <cuda_runtime.h>
#include <stdint.h>

#define NCLS 10
#define DD   128
#define WPB  4                    // warps per block
#define TPB  128
#define OCC  5                    // blocks per SM
#define NBLK (148 * OCC)          // 740, one wave
#define GR   8                    // rows per staged group
#define GB   (GR * DD * 4)        // 4096 B per group
// per-warp smem region: 2-deep ring (8192 B) reused as epilogue staging
#define WSTP   2048               // floats per warp region
#define W_RSSQ (NCLS * DD)        // 1280
#define W_CNT  (W_RSSQ + NCLS * 32) // 1600

// Zero-initialized at module load; finalizing block re-zeros after each use.
__device__ float g_sums[NCLS * DD];
__device__ float g_rssq[NCLS];
__device__ float g_cnt[NCLS];
__device__ unsigned int g_ticket;

__device__ __forceinline__ uint32_t s2u(const void* p) {
    uint32_t a;
    asm("{ .reg .u64 t; cvta.to.shared.u64 t, %1; cvt.u32.u64 %0, t; }"
        : "=r"(a) : "l"(p));
    return a;
}

__global__ __launch_bounds__(TPB, OCC) void acc_k(const float* __restrict__ x,
                                                  const int* __restrict__ t,
                                                  int n,
                                                  float* __restrict__ out) {
    __shared__ __align__(16) float sm[WPB * WSTP];   // 32 KB
    __shared__ bool s_last;
    const int lane = threadIdx.x & 31;
    const int warp = threadIdx.x >> 5;
    float* ws = sm + warp * WSTP;
    const uint32_t wbase = s2u(ws) + (uint32_t)lane * 16u;

    // ── register accumulators (constant-indexed via switch → stay in regs) ──
    float4 acc[NCLS];
    float  q[NCLS], cnt[NCLS];
#pragma unroll
    for (int c = 0; c < NCLS; c++) {
        acc[c] = make_float4(0.f, 0.f, 0.f, 0.f);
        q[c] = 0.f; cnt[c] = 0.f;
    }

    const int gw = blockIdx.x * WPB + warp;   // global warp id
    const int W  = NBLK * WPB;                // 2960 warps
    int chunk = (n + W - 1) / W;
    chunk = (chunk + GR - 1) & ~(GR - 1);     // multiple of 8
    const int start = gw * chunk;
    const int end   = (start + chunk < n) ? (start + chunk) : n;
    const int rows  = (end > start) ? (end - start) : 0;
    const int nfull = rows / GR;

    // stage group k (8 rows, 16 B per lane per row) into ring slot k&1
#define ISSUE(k) do {                                                        \
        const float* src_ = x + (size_t)(start + (k) * GR) * DD + lane * 4;  \
        const uint32_t dst_ = wbase + (((k) & 1) ? GB : 0);                  \
        _Pragma("unroll")                                                    \
        for (int r_ = 0; r_ < GR; r_++)                                      \
            asm volatile("cp.async.cg.shared.global [%0], [%1], 16;"         \
                         :: "r"(dst_ + r_ * 512), "l"(src_ + r_ * DD)        \
                         : "memory");                                        \
        asm volatile("cp.async.commit_group;" ::: "memory");                 \
    } while (0)

#define WAITG1() asm volatile("cp.async.wait_group 1;" ::: "memory")
#define WAITG0() asm volatile("cp.async.wait_group 0;" ::: "memory")

#define CASE(c) case c: acc[c].x += v.x; acc[c].y += v.y;                    \
                        acc[c].z += v.z; acc[c].w += v.w;                    \
                        q[c] += p; cnt[c] += 1.0f; break;

#define ROWV(lab, v) do {                                                    \
        float p = fmaf(v.x, v.x, fmaf(v.y, v.y, fmaf(v.z, v.z, v.w * v.w))); \
        switch (lab) { CASE(0) CASE(1) CASE(2) CASE(3) CASE(4)               \
                       CASE(5) CASE(6) CASE(7) CASE(8) CASE(9) }             \
    } while (0)

#define ROWS_SM(base, La, Lb) do {                                           \
        const float4* rp_ = (const float4*)(ws + 0) +                        \
                            (((base) - s2u(ws)) >> 4);                       \
        float4 v;                                                            \
        v = rp_[0 * 32];  ROWV(La.x, v);                                     \
        v = rp_[1 * 32];  ROWV(La.y, v);                                     \
        v = rp_[2 * 32];  ROWV(La.z, v);                                     \
        v = rp_[3 * 32];  ROWV(La.w, v);                                     \
        v = rp_[4 * 32];  ROWV(Lb.x, v);                                     \
        v = rp_[5 * 32];  ROWV(Lb.y, v);                                     \
        v = rp_[6 * 32];  ROWV(Lb.z, v);                                     \
        v = rp_[7 * 32];  ROWV(Lb.w, v);                                     \
    } while (0)

    if (nfull > 0) {
        // label buffers live in named regs per ring parity (no runtime array idx)
        int4 La0, Lb0, La1, Lb1;
        ISSUE(0);
        { const int4* tp = (const int4*)(t + start); La0 = __ldg(tp); Lb0 = __ldg(tp + 1); }
        if (nfull > 1) {
            ISSUE(1);
            const int4* tp = (const int4*)(t + start + GR);
            La1 = __ldg(tp); Lb1 = __ldg(tp + 1);
        }

        int k = 0;
        for (;;) {
            // even parity group
            if (k + 1 < nfull) WAITG1(); else WAITG0();
            ROWS_SM(wbase, La0, Lb0);
            __syncwarp();
            if (k + 2 < nfull) {
                ISSUE(k + 2);
                const int4* tp = (const int4*)(t + start + (k + 2) * GR);
                La0 = __ldg(tp); Lb0 = __ldg(tp + 1);
            }
            k++;
            if (k >= nfull) break;

            // odd parity group
            if (k + 1 < nfull) WAITG1(); else WAITG0();
            ROWS_SM(wbase + GB, La1, Lb1);
            __syncwarp();
            if (k + 2 < nfull) {
                ISSUE(k + 2);
                const int4* tp = (const int4*)(t + start + (k + 2) * GR);
                La1 = __ldg(tp); Lb1 = __ldg(tp + 1);
            }
            k++;
            if (k >= nfull) break;
        }
    }
    // tail rows (< GR) via plain loads
    for (int i = start + nfull * GR; i < end; i++) {
        const int lab = __ldg(t + i);
        const float4 v = __ldg((const float4*)(x + (size_t)i * DD) + lane);
        ROWV(lab, v);
    }

#undef ROWS_SM
#undef ROWV
#undef CASE
#undef ISSUE

    // ── stage registers into per-warp smem (write-once), then combine ──
    __syncthreads();   // all warps done with their rings; regions reusable
#pragma unroll
    for (int c = 0; c < NCLS; c++) {
        reinterpret_cast<float4*>(ws + c * DD)[lane] = acc[c];
        ws[W_RSSQ + c * 32 + lane] = q[c];
        if (lane == 0) ws[W_CNT + c] = cnt[c];
    }
    __syncthreads();

    for (int idx = threadIdx.x; idx < NCLS * DD; idx += TPB) {
        float s = 0.0f;
#pragma unroll
        for (int w = 0; w < WPB; w++) s += sm[w * WSTP + idx];
        atomicAdd(&g_sums[idx], s);
    }
    if (threadIdx.x < NCLS) {
        const int c = threadIdx.x;
        float r = 0.0f, cn = 0.0f;
#pragma unroll
        for (int w = 0; w < WPB; w++) {
            for (int l = 0; l < 32; l++) r += sm[w * WSTP + W_RSSQ + c * 32 + l];
            cn += sm[w * WSTP + W_CNT + c];
        }
        atomicAdd(&g_rssq[c], r);
        atomicAdd(&g_cnt[c], cn);
    }

    // ── last-block finalization (fused; proven pattern) ──
    __threadfence();
    if (threadIdx.x == 0)
        s_last = (atomicAdd(&g_ticket, 1u) == (unsigned)(gridDim.x - 1));
    __syncthreads();
    if (!s_last) return;

    float* cross = sm;
    if (threadIdx.x < NCLS) cross[threadIdx.x] = 0.0f;
    __syncthreads();
    {
        const int d = threadIdx.x;   // 128 threads, one per feature
#pragma unroll
        for (int c = 0; c < NCLS; c++) {
            const float s = g_sums[c * DD + d];
            atomicAdd(&cross[c], s * s);
            g_sums[c * DD + d] = 0.0f;   // re-zero for next replay
        }
    }
    __syncthreads();
    if (threadIdx.x == 0) {
        float a = 0.0f;
#pragma unroll
        for (int c = 0; c < NCLS; c++) {
            const float ncf = g_cnt[c];
            a += (g_rssq[c] - cross[c] / ncf) / (ncf - 1.0f);
            g_rssq[c] = 0.0f;
            g_cnt[c]  = 0.0f;
        }
        out[0] = a / (float)NCLS;
        g_ticket = 0u;
    }
}

extern "C" void kernel_launch(void* const* d_in, const int* in_sizes, int n_in,
                              void* d_out, int out_size) {
    const float* x = (const float*)d_in[0];   // x: [N, 128] fp32
    const int*   t = (const int*)d_in[1];     // t: [N] int32
    const int n = in_sizes[1];                // N = row count

    // make sure 5 blocks x 32 KB static smem can be resident per SM
    static bool configured = false;
    if (!configured) {
        cudaFuncSetAttribute(acc_k, cudaFuncAttributePreferredSharedMemoryCarveout,
                             cudaSharedmemCarveoutMaxShared);
        configured = true;
    }
    acc_k<<<NBLK, TPB>>>(x, t, n, (float*)d_out);
}